// round 17
// baseline (speedup 1.0000x reference)
#include <cuda_runtime.h>
#include <cstdint>

// ---------------------------------------------------------------------------
// SageLayer: out = relu(concat(features, segsum(features[col], row)/(deg+1)) @ W)
// features: f32 [N,64], row/col: int32 [E], W: f32 [128,128], out: f32 [N,128]
//
// K1: zero counters + transpose W -> tf32 Wt[n][k]  (~2us)
// K2: bucketed CSR build                            (~8us)
// K3 (FUSED into K4): persistent tf32 mma.sync GEMM where the A-tile staging
//     IS the neighbor-mean gather (smem-direct, no g_acc round trip).
//     Gather (LTS-bound) overlaps GEMM (HMMA-bound) via inter-CTA skew.
// ---------------------------------------------------------------------------

#define N_NODES_MAX 50176
#define CAP 96   // max neighbors kept (Poisson(16); P(>=96)~1e-44)

__device__ int g_cnt[N_NODES_MAX];
__device__ int g_csr[(size_t)N_NODES_MAX * CAP];
__device__ __align__(16) uint32_t g_Wt[128 * 128];   // W^T as tf32 bits

__device__ __forceinline__ uint32_t f2tf32(float x) {
    uint32_t r;
    asm("cvt.rna.tf32.f32 %0, %1;" : "=r"(r) : "f"(x));
    return r;
}

// ---------------------------------------------------------------------------
// K1: zero counters + transpose W to tf32 (16384 threads cover |W|)
// ---------------------------------------------------------------------------
__global__ void sage_prep_kernel(const float* __restrict__ W, int n) {
    int tid = blockIdx.x * blockDim.x + threadIdx.x;
    int stride = gridDim.x * blockDim.x;
    if (tid < 16384) {
        int nn = tid >> 7, k = tid & 127;
        g_Wt[tid] = f2tf32(__ldg(&W[k * 128 + nn]));
    }
    for (int i = tid; i < n; i += stride)
        g_cnt[i] = 0;
}

// ---------------------------------------------------------------------------
// K2: bucketed CSR build. One thread per edge.
// ---------------------------------------------------------------------------
__global__ void sage_build_kernel(const int* __restrict__ row,
                                  const int* __restrict__ col,
                                  int nedges) {
    int e = blockIdx.x * blockDim.x + threadIdx.x;
    if (e >= nedges) return;
    int r = __ldg(&row[e]);
    int c = __ldg(&col[e]);
    int pos = atomicAdd(&g_cnt[r], 1);
    if (pos < CAP)
        g_csr[(size_t)r * CAP + pos] = c;
}

// ---------------------------------------------------------------------------
// tf32 mma.sync helper (classic HMMA path — valid on plain sm_103 target)
// ---------------------------------------------------------------------------
__device__ __forceinline__ void mma_tf32(float* d, const uint32_t* a,
                                         const uint32_t* b) {
    asm volatile(
        "mma.sync.aligned.m16n8k8.row.col.f32.tf32.tf32.f32 "
        "{%0,%1,%2,%3}, {%4,%5,%6,%7}, {%8,%9}, {%0,%1,%2,%3};"
        : "+f"(d[0]), "+f"(d[1]), "+f"(d[2]), "+f"(d[3])
        : "r"(a[0]), "r"(a[1]), "r"(a[2]), "r"(a[3]),
          "r"(b[0]), "r"(b[1]));
}

#define SAS 132

// ---------------------------------------------------------------------------
// Gather one 128-row tile of the combined matrix [feat | neighbor-mean]
// straight into an smem tf32 buffer. 256 threads: thread (r = t>>1, h = t&1)
// copies feat float4 slots [8h,8h+8) and accumulates mean slots [8h,8h+8)
// over the row's neighbor list (MLP 8 per neighbor). Uniform work per thread.
// ---------------------------------------------------------------------------
__device__ __forceinline__ void gather_tile(
    uint32_t* __restrict__ buf, const float4* __restrict__ feat4,
    int tile, int n, int r, int h)
{
    int gr = tile * 128 + r;
    int sbase = 8 * h;              // float4 slot base within each half

    if (gr >= n) {
        #pragma unroll
        for (int j = 0; j < 8; j++) {
            uint4 z = make_uint4(0u, 0u, 0u, 0u);
            *reinterpret_cast<uint4*>(&buf[r * SAS + 4 * (sbase + j)]) = z;
            *reinterpret_cast<uint4*>(&buf[r * SAS + 4 * (16 + sbase + j)]) = z;
        }
        return;
    }

    // feature copy: combined slots [8h, 8h+8)
    const float4* srcf = feat4 + (size_t)gr * 16 + sbase;
    #pragma unroll
    for (int j = 0; j < 8; j++) {
        float4 v = __ldg(&srcf[j]);
        uint4 u;
        u.x = f2tf32(v.x); u.y = f2tf32(v.y);
        u.z = f2tf32(v.z); u.w = f2tf32(v.w);
        *reinterpret_cast<uint4*>(&buf[r * SAS + 4 * (sbase + j)]) = u;
    }

    // neighbor mean: combined slots [16+8h, 16+8h+8)
    int cnt = __ldg(&g_cnt[gr]);
    int len = cnt < CAP ? cnt : CAP;
    float inv = 1.0f / (float)(cnt + 1);
    const int* lst = g_csr + (size_t)gr * CAP;

    float4 s[8];
    #pragma unroll
    for (int j = 0; j < 8; j++)
        s[j] = make_float4(0.f, 0.f, 0.f, 0.f);

    for (int e = 0; e < len; e++) {
        int c = __ldg(&lst[e]);
        const float4* src = feat4 + (size_t)c * 16 + sbase;
        #pragma unroll
        for (int j = 0; j < 8; j++) {
            float4 v = __ldg(&src[j]);
            s[j].x += v.x; s[j].y += v.y; s[j].z += v.z; s[j].w += v.w;
        }
    }
    #pragma unroll
    for (int j = 0; j < 8; j++) {
        uint4 u;
        u.x = f2tf32(s[j].x * inv); u.y = f2tf32(s[j].y * inv);
        u.z = f2tf32(s[j].z * inv); u.w = f2tf32(s[j].w * inv);
        *reinterpret_cast<uint4*>(&buf[r * SAS + 4 * (16 + sbase + j)]) = u;
    }
}

// ---------------------------------------------------------------------------
// Fused persistent kernel: gather + tf32 mma.sync GEMM + ReLU.
// 256 threads, 128 rows/tile. smem: sB + 2x sA = 203 KB, occ 1.
// Warp grid 4x2 (R13/R15 verified): warp = 32 rows x 64 cols.
// Per iter: mainloop(cur) -> epilogue -> gather(next -> other buf) -> sync.
// ---------------------------------------------------------------------------
__global__ __launch_bounds__(256, 1)
void sage_fused_kernel(const float4* __restrict__ feat4,
                       float* __restrict__ out, int n, int ntiles) {
    extern __shared__ uint32_t sh[];
    uint32_t* sB  = sh;                   // 128*132
    uint32_t* sA0 = sh + 128 * SAS;       // 128*132
    uint32_t* sA1 = sh + 256 * SAS;       // 128*132

    int t = threadIdx.x;

    // ---- stage B once (tf32 Wt[n][k]): pure uint4 copy ----
    {
        int nr = t >> 1;
        int half = t & 1;
        const uint4* src = reinterpret_cast<const uint4*>(g_Wt) +
                           (size_t)nr * 32 + half * 16;
        #pragma unroll
        for (int j = 0; j < 16; j++) {
            uint4 u = __ldg(&src[j]);
            *reinterpret_cast<uint4*>(&sB[nr * SAS + half * 64 + 4 * j]) = u;
        }
    }

    int r = t >> 1;
    int h = t & 1;

    // ---- gather first tile into sA0 ----
    int tile = blockIdx.x;
    if (tile < ntiles)
        gather_tile(sA0, feat4, tile, n, r, h);
    __syncthreads();

    int wid = t >> 5;
    int lane = t & 31;
    int warp_m = wid & 3;          // rows [32*warp_m, +32)
    int warp_n = wid >> 2;         // cols [64*warp_n, +64)
    int t4 = lane >> 2;            // 0..7
    int tm = lane & 3;             // 0..3
    int arow = warp_m * 32 + t4;
    int brow = warp_n * 64 + t4;

    int it = 0;
    while (tile < ntiles) {
        int next = tile + gridDim.x;
        uint32_t* cur = (it & 1) ? sA1 : sA0;

        // ---- mainloop (verified layout) ----
        float acc[2][8][4];
        #pragma unroll
        for (int mt = 0; mt < 2; mt++)
            #pragma unroll
            for (int nt = 0; nt < 8; nt++)
                #pragma unroll
                for (int i = 0; i < 4; i++)
                    acc[mt][nt][i] = 0.f;

        #pragma unroll
        for (int ks = 0; ks < 16; ks++) {
            int k0 = ks * 8;
            uint32_t a[2][4];
            #pragma unroll
            for (int mt = 0; mt < 2; mt++) {
                const uint32_t* p = &cur[(arow + mt * 16) * SAS + k0 + tm];
                a[mt][0] = p[0];
                a[mt][1] = p[8 * SAS];
                a[mt][2] = p[4];
                a[mt][3] = p[8 * SAS + 4];
            }
            uint32_t b[8][2];
            #pragma unroll
            for (int nt = 0; nt < 8; nt++) {
                const uint32_t* p = &sB[(brow + nt * 8) * SAS + k0 + tm];
                b[nt][0] = p[0];
                b[nt][1] = p[4];
            }
            #pragma unroll
            for (int mt = 0; mt < 2; mt++)
                #pragma unroll
                for (int nt = 0; nt < 8; nt++)
                    mma_tf32(acc[mt][nt], a[mt], b[nt]);
        }

        // ---- epilogue: ReLU + store current tile ----
        {
            int row0 = tile * 128;
            #pragma unroll
            for (int mt = 0; mt < 2; mt++) {
                int r0 = row0 + warp_m * 32 + mt * 16 + t4;
                int r1 = r0 + 8;
                #pragma unroll
                for (int nt = 0; nt < 8; nt++) {
                    int c = warp_n * 64 + nt * 8 + 2 * tm;
                    if (r0 < n) {
                        float2 o;
                        o.x = fmaxf(acc[mt][nt][0], 0.f);
                        o.y = fmaxf(acc[mt][nt][1], 0.f);
                        *reinterpret_cast<float2*>(&out[(size_t)r0 * 128 + c]) = o;
                    }
                    if (r1 < n) {
                        float2 o;
                        o.x = fmaxf(acc[mt][nt][2], 0.f);
                        o.y = fmaxf(acc[mt][nt][3], 0.f);
                        *reinterpret_cast<float2*>(&out[(size_t)r1 * 128 + c]) = o;
                    }
                }
            }
        }

        // ---- gather next tile into the other buffer ----
        // (other buffer's last reader was the mainloop BEFORE the previous
        //  __syncthreads, so writing it here is hazard-free)
        if (next < ntiles) {
            uint32_t* nxt = (it & 1) ? sA0 : sA1;
            gather_tile(nxt, feat4, next, n, r, h);
        }
        __syncthreads();

        tile = next;
        it++;
    }
}

// ---------------------------------------------------------------------------
// Launch
// ---------------------------------------------------------------------------
extern "C" void kernel_launch(void* const* d_in, const int* in_sizes, int n_in,
                              void* d_out, int out_size) {
    const float* feat = (const float*)d_in[0];   // [N,64]
    const int* row = (const int*)d_in[1];        // [E] int32
    const int* col = (const int*)d_in[2];        // [E] int32
    const float* W = (const float*)d_in[3];      // [128,128]
    float* out = (float*)d_out;                  // [N,128]

    int n = in_sizes[0] / 64;
    int nedges = in_sizes[1];

    // K1: zero counters + transpose W to tf32
    sage_prep_kernel<<<64, 256>>>(W, n);

    // K2: bucketed CSR build
    sage_build_kernel<<<(nedges + 255) / 256, 256>>>(row, col, nedges);

    // Fused gather + GEMM + ReLU (persistent, double-buffered)
    {
        int ntiles = (n + 127) / 128;
        int smem = 3 * 128 * SAS * sizeof(uint32_t);  // 202.75 KB
        cudaFuncSetAttribute(sage_fused_kernel,
                             cudaFuncAttributeMaxDynamicSharedMemorySize, smem);
        sage_fused_kernel<<<148, 256, smem>>>(
            reinterpret_cast<const float4*>(feat), out, n, ntiles);
    }
}